// round 13
// baseline (speedup 1.0000x reference)
#include <cuda_runtime.h>

// GraphAppnp: fused sum-aggregation + APPNP alpha blend. HBM-bound streaming.
// R13 = R10 + interleaved load order (a0,b0,a1,b1) + early store of b0 so
// write injection is spread between reads instead of phase-synchronized.
// v8 (256-bit) ops: every warp memory instruction is one 1KB fully-contiguous
// block. 4 warps co-stream one node's 8KB region (warp w: node w/4,
// k-quarter w%4); lane l covers 32B; one v8 instr covers 4 k-rows.
// Inputs: x[N,D], neighbor_agg[N,K,D], h[N,D], neighbor[N,K,D]
// Outputs (concat): x_out[N,D] then nbr_out[N,K,D]
// N=50000, K=32, D=64, ALPHA=0.1

#define ALPHA     0.1f
#define ONE_M_A   0.9f
#define KNBR      32
#define DDIM      64
#define ROWF      64             // floats per row
#define NODEF     (KNBR * ROWF)  // 2048 floats per node region

__device__ __forceinline__ void ldg_cs_v8(const float* p, float* v) {
    asm("ld.global.cs.v8.f32 {%0,%1,%2,%3,%4,%5,%6,%7}, [%8];"
        : "=f"(v[0]), "=f"(v[1]), "=f"(v[2]), "=f"(v[3]),
          "=f"(v[4]), "=f"(v[5]), "=f"(v[6]), "=f"(v[7])
        : "l"(p));
}

__device__ __forceinline__ void ldg_v8(const float* p, float* v) {
    asm("ld.global.v8.f32 {%0,%1,%2,%3,%4,%5,%6,%7}, [%8];"
        : "=f"(v[0]), "=f"(v[1]), "=f"(v[2]), "=f"(v[3]),
          "=f"(v[4]), "=f"(v[5]), "=f"(v[6]), "=f"(v[7])
        : "l"(p));
}

__device__ __forceinline__ void stg_cs_v8(float* p, const float* v) {
    asm volatile("st.global.cs.v8.f32 [%0], {%1,%2,%3,%4,%5,%6,%7,%8};"
        :: "l"(p),
           "f"(v[0]), "f"(v[1]), "f"(v[2]), "f"(v[3]),
           "f"(v[4]), "f"(v[5]), "f"(v[6]), "f"(v[7])
        : "memory");
}

__global__ __launch_bounds__(256)
void appnp_fused_kernel(const float* __restrict__ x,
                        const float* __restrict__ nagg,
                        const float* __restrict__ h,
                        const float* __restrict__ nbr,
                        float* __restrict__ out_x,
                        float* __restrict__ out_nbr,
                        int n_nodes)
{
    __shared__ float4 sacc4[8][16];  // [warp][float4-d-index] partial sums (2KB)

    int wid  = threadIdx.x >> 5;     // 0..7
    int lane = threadIdx.x & 31;
    int nloc = wid >> 2;             // 0..1  node within CTA
    int kq   = wid & 3;              // 0..3  k-quarter within node
    int d8   = lane & 7;             // which 8-float d-slice this lane owns

    int node = blockIdx.x * 2 + nloc;
    if (node >= n_nodes) return;     // n_nodes even (50000), whole CTA uniform

    // warp covers rows [kq*8, kq*8+8); v8 instr j covers rows kq*8+j*4..+4
    // lane l handles bytes [32l, 32l+32) of each 1KB block
    size_t base = (size_t)node * NODEF + (size_t)kq * (8 * ROWF) + (size_t)lane * 8;
    const float* na_p  = nagg    + base;
    const float* nb_p  = nbr     + base;
    float*       out_p = out_nbr + base;

    // x d-slice for this lane (shared by the 4 rows the lane touches)
    const float* xp = x + (size_t)node * ROWF + (size_t)d8 * 8;
    float xv[8];
    ldg_v8(xp, xv);

    // interleaved stream order: a0, b0, a1, b1
    float a0[8], a1[8], b0[8], b1[8];
    ldg_cs_v8(na_p,             a0);   // 1KB contiguous per warp instr
    ldg_cs_v8(nb_p,             b0);
    ldg_cs_v8(na_p + 4 * ROWF,  a1);
    ldg_cs_v8(nb_p + 4 * ROWF,  b1);

    float acc[8];

    // compute + store first half immediately: spreads write injection
    #pragma unroll
    for (int i = 0; i < 8; ++i) {
        acc[i] = a0[i];
        b0[i] = fmaf(ONE_M_A, a0[i] + xv[i], ALPHA * b0[i]);
    }
    stg_cs_v8(out_p, b0);

    #pragma unroll
    for (int i = 0; i < 8; ++i) {
        acc[i] += a1[i];
        b1[i] = fmaf(ONE_M_A, a1[i] + xv[i], ALPHA * b1[i]);
    }
    stg_cs_v8(out_p + 4 * ROWF, b1);

    // reduce acc across the 4 lanes sharing this d-slice (l, l^8, l^16, l^24)
    #pragma unroll
    for (int i = 0; i < 8; ++i) {
        acc[i] += __shfl_xor_sync(0xffffffffu, acc[i], 8);
        acc[i] += __shfl_xor_sync(0xffffffffu, acc[i], 16);
    }

    if (lane < 8) {
        sacc4[wid][lane * 2]     = make_float4(acc[0], acc[1], acc[2], acc[3]);
        sacc4[wid][lane * 2 + 1] = make_float4(acc[4], acc[5], acc[6], acc[7]);
    }
    __syncthreads();

    // warp 0 finalizes node 0, warp 1 finalizes node 1 (lanes 0-15 active)
    if (wid < 2 && lane < 16) {
        int nl = wid;
        float4 s = make_float4(0.f, 0.f, 0.f, 0.f);
        #pragma unroll
        for (int j = 0; j < 4; ++j) {
            float4 v = sacc4[nl * 4 + j][lane];
            s.x += v.x; s.y += v.y; s.z += v.z; s.w += v.w;
        }
        int fnode = blockIdx.x * 2 + nl;
        size_t fr = (size_t)fnode * ROWF + (size_t)lane * 4;
        float4 xf = *(const float4*)(x + fr);
        float4 hv = *(const float4*)(h + fr);
        float4 xo;
        xo.x = fmaf(ONE_M_A, xf.x + s.x, ALPHA * hv.x);
        xo.y = fmaf(ONE_M_A, xf.y + s.y, ALPHA * hv.y);
        xo.z = fmaf(ONE_M_A, xf.z + s.z, ALPHA * hv.z);
        xo.w = fmaf(ONE_M_A, xf.w + s.w, ALPHA * hv.w);
        *(float4*)(out_x + fr) = xo;
    }
}

extern "C" void kernel_launch(void* const* d_in, const int* in_sizes, int n_in,
                              void* d_out, int out_size)
{
    const float* x    = (const float*)d_in[0];
    const float* nagg = (const float*)d_in[1];
    const float* h    = (const float*)d_in[2];
    const float* nbr  = (const float*)d_in[3];

    int n_nodes = in_sizes[0] / DDIM;

    float* out_x   = (float*)d_out;
    float* out_nbr = (float*)d_out + (size_t)n_nodes * DDIM;

    int grid = (n_nodes + 1) / 2;    // 2 nodes per CTA

    appnp_fused_kernel<<<grid, 256>>>(x, nagg, h, nbr, out_x, out_nbr, n_nodes);
}

// round 14
// speedup vs baseline: 1.0225x; 1.0225x over previous
#include <cuda_runtime.h>

// GraphAppnp: fused sum-aggregation + APPNP alpha blend. HBM-bound streaming.
// FINAL (= R10, best of 13 rounds: 180.3us, 7.11 TB/s, 88.9% of HBM spec).
// v8 (256-bit) memory ops: every warp memory instruction is one 1KB
// fully-contiguous block. 4 warps co-stream one node's 8KB region
// (warp w: node w/4, k-quarter w%4); lane l covers 32B, so one v8 instr
// covers 4 k-rows; each warp: 2 v8-loads per stream + 2 v8-stores, all 4
// loads issued before any store (max MLP).
// Inputs: x[N,D], neighbor_agg[N,K,D], h[N,D], neighbor[N,K,D]
// Outputs (concat): x_out[N,D] then nbr_out[N,K,D]
// N=50000, K=32, D=64, ALPHA=0.1

#define ALPHA     0.1f
#define ONE_M_A   0.9f
#define KNBR      32
#define DDIM      64
#define ROWF      64             // floats per row
#define NODEF     (KNBR * ROWF)  // 2048 floats per node region

__device__ __forceinline__ void ldg_cs_v8(const float* p, float* v) {
    asm("ld.global.cs.v8.f32 {%0,%1,%2,%3,%4,%5,%6,%7}, [%8];"
        : "=f"(v[0]), "=f"(v[1]), "=f"(v[2]), "=f"(v[3]),
          "=f"(v[4]), "=f"(v[5]), "=f"(v[6]), "=f"(v[7])
        : "l"(p));
}

__device__ __forceinline__ void ldg_v8(const float* p, float* v) {
    asm("ld.global.v8.f32 {%0,%1,%2,%3,%4,%5,%6,%7}, [%8];"
        : "=f"(v[0]), "=f"(v[1]), "=f"(v[2]), "=f"(v[3]),
          "=f"(v[4]), "=f"(v[5]), "=f"(v[6]), "=f"(v[7])
        : "l"(p));
}

__device__ __forceinline__ void stg_cs_v8(float* p, const float* v) {
    asm volatile("st.global.cs.v8.f32 [%0], {%1,%2,%3,%4,%5,%6,%7,%8};"
        :: "l"(p),
           "f"(v[0]), "f"(v[1]), "f"(v[2]), "f"(v[3]),
           "f"(v[4]), "f"(v[5]), "f"(v[6]), "f"(v[7])
        : "memory");
}

__global__ __launch_bounds__(256)
void appnp_fused_kernel(const float* __restrict__ x,
                        const float* __restrict__ nagg,
                        const float* __restrict__ h,
                        const float* __restrict__ nbr,
                        float* __restrict__ out_x,
                        float* __restrict__ out_nbr,
                        int n_nodes)
{
    __shared__ float4 sacc4[8][16];  // [warp][float4-d-index] partial sums (2KB)

    int wid  = threadIdx.x >> 5;     // 0..7
    int lane = threadIdx.x & 31;
    int nloc = wid >> 2;             // 0..1  node within CTA
    int kq   = wid & 3;              // 0..3  k-quarter within node
    int d8   = lane & 7;             // which 8-float d-slice this lane owns

    int node = blockIdx.x * 2 + nloc;
    if (node >= n_nodes) return;     // n_nodes even (50000), whole CTA uniform

    // warp covers rows [kq*8, kq*8+8); v8 instr j covers rows kq*8+j*4..+4
    // lane l handles bytes [32l, 32l+32) of each 1KB block
    size_t base = (size_t)node * NODEF + (size_t)kq * (8 * ROWF) + (size_t)lane * 8;
    const float* na_p  = nagg    + base;
    const float* nb_p  = nbr     + base;
    float*       out_p = out_nbr + base;

    // x d-slice for this lane (shared by the 4 rows the lane touches)
    const float* xp = x + (size_t)node * ROWF + (size_t)d8 * 8;
    float xv[8];
    ldg_v8(xp, xv);

    float a0[8], a1[8], b0[8], b1[8];
    ldg_cs_v8(na_p,             a0);   // 1KB contiguous per warp instr
    ldg_cs_v8(na_p + 4 * ROWF,  a1);
    ldg_cs_v8(nb_p,             b0);
    ldg_cs_v8(nb_p + 4 * ROWF,  b1);

    float acc[8];
    #pragma unroll
    for (int i = 0; i < 8; ++i) {
        acc[i] = a0[i] + a1[i];
        b0[i] = fmaf(ONE_M_A, a0[i] + xv[i], ALPHA * b0[i]);
        b1[i] = fmaf(ONE_M_A, a1[i] + xv[i], ALPHA * b1[i]);
    }

    stg_cs_v8(out_p,            b0);   // 1KB contiguous per warp instr
    stg_cs_v8(out_p + 4 * ROWF, b1);

    // reduce acc across the 4 lanes sharing this d-slice (l, l^8, l^16, l^24)
    #pragma unroll
    for (int i = 0; i < 8; ++i) {
        acc[i] += __shfl_xor_sync(0xffffffffu, acc[i], 8);
        acc[i] += __shfl_xor_sync(0xffffffffu, acc[i], 16);
    }

    if (lane < 8) {
        sacc4[wid][lane * 2]     = make_float4(acc[0], acc[1], acc[2], acc[3]);
        sacc4[wid][lane * 2 + 1] = make_float4(acc[4], acc[5], acc[6], acc[7]);
    }
    __syncthreads();

    // warp 0 finalizes node 0, warp 1 finalizes node 1 (lanes 0-15 active)
    if (wid < 2 && lane < 16) {
        int nl = wid;
        float4 s = make_float4(0.f, 0.f, 0.f, 0.f);
        #pragma unroll
        for (int j = 0; j < 4; ++j) {
            float4 v = sacc4[nl * 4 + j][lane];
            s.x += v.x; s.y += v.y; s.z += v.z; s.w += v.w;
        }
        int fnode = blockIdx.x * 2 + nl;
        size_t fr = (size_t)fnode * ROWF + (size_t)lane * 4;
        float4 xf = *(const float4*)(x + fr);
        float4 hv = *(const float4*)(h + fr);
        float4 xo;
        xo.x = fmaf(ONE_M_A, xf.x + s.x, ALPHA * hv.x);
        xo.y = fmaf(ONE_M_A, xf.y + s.y, ALPHA * hv.y);
        xo.z = fmaf(ONE_M_A, xf.z + s.z, ALPHA * hv.z);
        xo.w = fmaf(ONE_M_A, xf.w + s.w, ALPHA * hv.w);
        *(float4*)(out_x + fr) = xo;
    }
}

extern "C" void kernel_launch(void* const* d_in, const int* in_sizes, int n_in,
                              void* d_out, int out_size)
{
    const float* x    = (const float*)d_in[0];
    const float* nagg = (const float*)d_in[1];
    const float* h    = (const float*)d_in[2];
    const float* nbr  = (const float*)d_in[3];

    int n_nodes = in_sizes[0] / DDIM;

    float* out_x   = (float*)d_out;
    float* out_nbr = (float*)d_out + (size_t)n_nodes * DDIM;

    int grid = (n_nodes + 1) / 2;    // 2 nodes per CTA

    appnp_fused_kernel<<<grid, 256>>>(x, nagg, h, nbr, out_x, out_nbr, n_nodes);
}

// round 15
// speedup vs baseline: 1.0340x; 1.0113x over previous
#include <cuda_runtime.h>

// GraphAppnp: fused sum-aggregation + APPNP alpha blend. HBM-bound streaming.
// R15 = R10 structure with 512-thread CTAs covering 4 adjacent nodes:
// each CTA sweeps a 32KB contiguous span per stream (cross-node locality),
// while keeping the proven 4-warps-per-node co-streaming and per-warp shape
// (v8 256-bit ops; every warp memory instruction = 1KB contiguous; 2 v8-loads
// per stream + 2 v8-stores; all 4 loads in flight before any store).
// Inputs: x[N,D], neighbor_agg[N,K,D], h[N,D], neighbor[N,K,D]
// Outputs (concat): x_out[N,D] then nbr_out[N,K,D]
// N=50000, K=32, D=64, ALPHA=0.1

#define ALPHA     0.1f
#define ONE_M_A   0.9f
#define KNBR      32
#define DDIM      64
#define ROWF      64             // floats per row
#define NODEF     (KNBR * ROWF)  // 2048 floats per node region
#define NPC       4              // nodes per CTA
#define CTA       512

__device__ __forceinline__ void ldg_cs_v8(const float* p, float* v) {
    asm("ld.global.cs.v8.f32 {%0,%1,%2,%3,%4,%5,%6,%7}, [%8];"
        : "=f"(v[0]), "=f"(v[1]), "=f"(v[2]), "=f"(v[3]),
          "=f"(v[4]), "=f"(v[5]), "=f"(v[6]), "=f"(v[7])
        : "l"(p));
}

__device__ __forceinline__ void ldg_v8(const float* p, float* v) {
    asm("ld.global.v8.f32 {%0,%1,%2,%3,%4,%5,%6,%7}, [%8];"
        : "=f"(v[0]), "=f"(v[1]), "=f"(v[2]), "=f"(v[3]),
          "=f"(v[4]), "=f"(v[5]), "=f"(v[6]), "=f"(v[7])
        : "l"(p));
}

__device__ __forceinline__ void stg_cs_v8(float* p, const float* v) {
    asm volatile("st.global.cs.v8.f32 [%0], {%1,%2,%3,%4,%5,%6,%7,%8};"
        :: "l"(p),
           "f"(v[0]), "f"(v[1]), "f"(v[2]), "f"(v[3]),
           "f"(v[4]), "f"(v[5]), "f"(v[6]), "f"(v[7])
        : "memory");
}

__global__ __launch_bounds__(CTA)
void appnp_fused_kernel(const float* __restrict__ x,
                        const float* __restrict__ nagg,
                        const float* __restrict__ h,
                        const float* __restrict__ nbr,
                        float* __restrict__ out_x,
                        float* __restrict__ out_nbr,
                        int n_nodes)
{
    __shared__ float4 sacc4[16][16]; // [warp][float4-d-index] partial sums (4KB)

    int wid  = threadIdx.x >> 5;     // 0..15
    int lane = threadIdx.x & 31;
    int nloc = wid >> 2;             // 0..3  node within CTA
    int kq   = wid & 3;              // 0..3  k-quarter within node
    int d8   = lane & 7;             // which 8-float d-slice this lane owns

    int node = blockIdx.x * NPC + nloc;
    if (node >= n_nodes) return;     // n_nodes % 4 == 0 (50000): CTA uniform

    // warp covers rows [kq*8, kq*8+8); v8 instr j covers rows kq*8+j*4..+4
    // lane l handles bytes [32l, 32l+32) of each 1KB block
    size_t base = (size_t)node * NODEF + (size_t)kq * (8 * ROWF) + (size_t)lane * 8;
    const float* na_p  = nagg    + base;
    const float* nb_p  = nbr     + base;
    float*       out_p = out_nbr + base;

    // x d-slice for this lane (shared by the 4 rows the lane touches)
    const float* xp = x + (size_t)node * ROWF + (size_t)d8 * 8;
    float xv[8];
    ldg_v8(xp, xv);

    float a0[8], a1[8], b0[8], b1[8];
    ldg_cs_v8(na_p,             a0);   // 1KB contiguous per warp instr
    ldg_cs_v8(na_p + 4 * ROWF,  a1);
    ldg_cs_v8(nb_p,             b0);
    ldg_cs_v8(nb_p + 4 * ROWF,  b1);

    float acc[8];
    #pragma unroll
    for (int i = 0; i < 8; ++i) {
        acc[i] = a0[i] + a1[i];
        b0[i] = fmaf(ONE_M_A, a0[i] + xv[i], ALPHA * b0[i]);
        b1[i] = fmaf(ONE_M_A, a1[i] + xv[i], ALPHA * b1[i]);
    }

    stg_cs_v8(out_p,            b0);   // 1KB contiguous per warp instr
    stg_cs_v8(out_p + 4 * ROWF, b1);

    // reduce acc across the 4 lanes sharing this d-slice (l, l^8, l^16, l^24)
    #pragma unroll
    for (int i = 0; i < 8; ++i) {
        acc[i] += __shfl_xor_sync(0xffffffffu, acc[i], 8);
        acc[i] += __shfl_xor_sync(0xffffffffu, acc[i], 16);
    }

    if (lane < 8) {
        sacc4[wid][lane * 2]     = make_float4(acc[0], acc[1], acc[2], acc[3]);
        sacc4[wid][lane * 2 + 1] = make_float4(acc[4], acc[5], acc[6], acc[7]);
    }
    __syncthreads();

    // warps 0..3 finalize nodes 0..3 (lanes 0-15 active)
    if (wid < NPC && lane < 16) {
        int nl = wid;
        float4 s = make_float4(0.f, 0.f, 0.f, 0.f);
        #pragma unroll
        for (int j = 0; j < 4; ++j) {
            float4 v = sacc4[nl * 4 + j][lane];
            s.x += v.x; s.y += v.y; s.z += v.z; s.w += v.w;
        }
        int fnode = blockIdx.x * NPC + nl;
        size_t fr = (size_t)fnode * ROWF + (size_t)lane * 4;
        float4 xf = *(const float4*)(x + fr);
        float4 hv = *(const float4*)(h + fr);
        float4 xo;
        xo.x = fmaf(ONE_M_A, xf.x + s.x, ALPHA * hv.x);
        xo.y = fmaf(ONE_M_A, xf.y + s.y, ALPHA * hv.y);
        xo.z = fmaf(ONE_M_A, xf.z + s.z, ALPHA * hv.z);
        xo.w = fmaf(ONE_M_A, xf.w + s.w, ALPHA * hv.w);
        *(float4*)(out_x + fr) = xo;
    }
}

extern "C" void kernel_launch(void* const* d_in, const int* in_sizes, int n_in,
                              void* d_out, int out_size)
{
    const float* x    = (const float*)d_in[0];
    const float* nagg = (const float*)d_in[1];
    const float* h    = (const float*)d_in[2];
    const float* nbr  = (const float*)d_in[3];

    int n_nodes = in_sizes[0] / DDIM;

    float* out_x   = (float*)d_out;
    float* out_nbr = (float*)d_out + (size_t)n_nodes * DDIM;

    int grid = (n_nodes + NPC - 1) / NPC;   // 4 nodes per CTA

    appnp_fused_kernel<<<grid, CTA>>>(x, nagg, h, nbr, out_x, out_nbr, n_nodes);
}